// round 12
// baseline (speedup 1.0000x reference)
#include <cuda_runtime.h>
#include <stdint.h>

#define EE     100000
#define DIN    192
#define KNB    8

// ---------------- scratch (device globals) ----------------
__device__ float g_qkv[EE * DIN];   // [E,192] = [q|k|v]
__device__ float g_ef1[EE * 64];    // [E,64] layer-1 out

// ---------------- helpers ----------------
__device__ __forceinline__ uint32_t f2tf(float x) {
    uint32_t u; asm("cvt.rna.tf32.f32 %0, %1;" : "=r"(u) : "f"(x)); return u;
}
__device__ __forceinline__ void mma8(float* c, const uint32_t* a, uint32_t b0, uint32_t b1) {
    asm volatile("mma.sync.aligned.m16n8k8.row.col.f32.tf32.tf32.f32 "
        "{%0,%1,%2,%3}, {%4,%5,%6,%7}, {%8,%9}, {%0,%1,%2,%3};"
        : "+f"(c[0]), "+f"(c[1]), "+f"(c[2]), "+f"(c[3])
        : "r"(a[0]), "r"(a[1]), "r"(a[2]), "r"(a[3]), "r"(b0), "r"(b1));
}
__device__ __forceinline__ void ldsm4(uint32_t* f, uint32_t addr) {
    asm volatile("ldmatrix.sync.aligned.m8n8.x4.shared.b16 {%0,%1,%2,%3}, [%4];"
        : "=r"(f[0]), "=r"(f[1]), "=r"(f[2]), "=r"(f[3]) : "r"(addr));
}

// ---------------- QKV kernel smem geometry (r4/r9 proven) ----------------
#define BSTRIDE    200
#define B_WORDS_F  (192 * BSTRIDE)      // 38400
#define A_WORDS    (128 * 36)           // 4608
#define QKV_SMEM_BYTES ((B_WORDS_F + 2 * A_WORDS) * 4)

// ---------------- fused attn+wo smem geometry ----------------
#define FSTRIDE    68                    // 68 % 32 == 4 -> conflict-free ldsm/STS
#define FA_WORDS   (128 * FSTRIDE)       // 8704
#define FB_WORDS   (64 * FSTRIDE)        // 4352
#define FUSED_SMEM_BYTES ((FA_WORDS + FB_WORDS) * 4)   // 52224

// ======================================================================
// Fused QKV GEMM (r4/r9 proven): qkv = concat(ef|ef1, nf[src], nf[dst]) @ [Wq|Wk|Wv]
// BM=128, BN=192, BK=32; 8 warps as 2M x 4N, warp tile 64x48.
// ======================================================================
__global__ __launch_bounds__(256, 1) void qkv_mma_kernel(
    const float* __restrict__ ef, const float* __restrict__ nf,
    const int* __restrict__ ei,
    const float* __restrict__ wq, const float* __restrict__ wk, const float* __restrict__ wv,
    int use_ef1)
{
    extern __shared__ uint32_t smem[];
    uint32_t* Bs = smem;                 // [192][200]
    uint32_t* As = smem + B_WORDS_F;     // [2][128*36]

    const int tid = threadIdx.x;
    const int m0  = blockIdx.x * 128;
    const float* efsrc = use_ef1 ? (const float*)g_ef1 : ef;

    const int r  = tid >> 1;
    const int e  = m0 + r;
    const int kb = (tid & 1) * 16;
    const bool valid = (e < EE);
    int si = 0, di = 0;
    if (valid) { si = ei[e]; di = ei[EE + e]; }

    const int wid = tid >> 5, lane = tid & 31;
    const int wm = (wid & 1) * 64, wn = (wid >> 1) * 48;
    const int g = lane >> 2, t4 = lane & 3;
    const int j8 = lane & 7, grp = lane >> 3;

    // ---- preload full B into smem (tf32) ----
    {
        #pragma unroll
        for (int w = 0; w < 3; w++) {
            const float* W = (w == 0) ? wq : (w == 1) ? wk : wv;
            #pragma unroll
            for (int j = 0; j < 12; j++) {
                int f = j * 256 + tid;
                int k = f >> 4;
                int n4 = (f & 15) * 4;
                float4 v = *reinterpret_cast<const float4*>(W + (size_t)k * 64 + n4);
                uint32_t* dst = Bs + k * BSTRIDE + w * 64 + n4;
                dst[0] = f2tf(v.x); dst[1] = f2tf(v.y);
                dst[2] = f2tf(v.z); dst[3] = f2tf(v.w);
            }
        }
    }

    const uint32_t As_b = (uint32_t)__cvta_generic_to_shared(As);
    uint32_t aAddr[4];
    #pragma unroll
    for (int mt = 0; mt < 4; mt++) {
        int row = wm + mt * 16 + (grp & 1) * 8 + j8;
        int col = (grp >> 1) * 4;
        aAddr[mt] = As_b + (row * 36 + col) * 4;
    }

    float acc[4][6][4];
    #pragma unroll
    for (int i = 0; i < 4; i++)
        #pragma unroll
        for (int j = 0; j < 6; j++)
            #pragma unroll
            for (int q = 0; q < 4; q++) acc[i][j][q] = 0.f;

    float4 av[4];
    auto ldg_tile = [&](int it) {
        const int k0 = it * 32;
        if (valid) {
            const int reg = k0 >> 6;
            const float* base = (reg == 0) ? efsrc + (size_t)e * 64
                              : (reg == 1) ? nf + (size_t)si * 64
                                           : nf + (size_t)di * 64;
            const int cb = (k0 & 32) + kb;
            #pragma unroll
            for (int c = 0; c < 4; c++) av[c] = *reinterpret_cast<const float4*>(base + cb + c * 4);
        } else {
            #pragma unroll
            for (int c = 0; c < 4; c++) av[c] = make_float4(0.f, 0.f, 0.f, 0.f);
        }
    };
    auto sts_tile = [&](int b) {
        uint32_t* Aw = As + b * A_WORDS;
        #pragma unroll
        for (int c = 0; c < 4; c++) {
            uint4 u = make_uint4(f2tf(av[c].x), f2tf(av[c].y), f2tf(av[c].z), f2tf(av[c].w));
            *reinterpret_cast<uint4*>(&Aw[r * 36 + kb + c * 4]) = u;
        }
    };

    const uint32_t* Bwp = Bs + wn + g;

    const int NIT = DIN / 32;   // 6
    ldg_tile(0);
    sts_tile(0);
    ldg_tile(1);
    __syncthreads();

    for (int i = 0; i < NIT; i++) {
        const int cur = i & 1;
        const uint32_t aOff = cur * (A_WORDS * 4);
        #pragma unroll
        for (int ks = 0; ks < 4; ks++) {
            const int kg = i * 32 + ks * 8 + t4;
            uint32_t af[4][4];
            #pragma unroll
            for (int mt = 0; mt < 4; mt++) ldsm4(af[mt], aAddr[mt] + aOff + ks * 32);
            uint32_t b0[6], b1[6];
            #pragma unroll
            for (int nt = 0; nt < 6; nt++) {
                b0[nt] = Bwp[kg * BSTRIDE + nt * 8];
                b1[nt] = Bwp[(kg + 4) * BSTRIDE + nt * 8];
            }
            #pragma unroll
            for (int mt = 0; mt < 4; mt++)
                #pragma unroll
                for (int nt = 0; nt < 6; nt++)
                    mma8(acc[mt][nt], af[mt], b0[nt], b1[nt]);
        }
        if (i + 1 < NIT) {
            sts_tile(cur ^ 1);
            if (i + 2 < NIT) ldg_tile(i + 2);
            __syncthreads();
        }
    }

    #pragma unroll
    for (int mt = 0; mt < 4; mt++) {
        const int row = m0 + wm + mt * 16 + g;
        #pragma unroll
        for (int nt = 0; nt < 6; nt++) {
            const int col = wn + nt * 8 + t4 * 2;
            if (row < EE)
                *reinterpret_cast<float2*>(g_qkv + (size_t)row * DIN + col) =
                    make_float2(acc[mt][nt][0], acc[mt][nt][1]);
            if (row + 8 < EE)
                *reinterpret_cast<float2*>(g_qkv + (size_t)(row + 8) * DIN + col) =
                    make_float2(acc[mt][nt][2], acc[mt][nt][3]);
        }
    }
}

// ======================================================================
// FUSED attention + Wo GEMM + residual — minimal-register attn, 4 CTAs/SM.
// Phase 1: 128 dst edges/CTA, attention -> As tf32 (nb indices re-read per pass)
// Phase 2: out = ef_in + As[128,64] @ Wo[64,64]
// ======================================================================
__global__ __launch_bounds__(256, 4) void attn_wo_kernel(
    const float* __restrict__ Wo,
    const int* __restrict__ adj_src,
    const float* __restrict__ ef_ext, float* __restrict__ out_ext,
    int use_ef1_in, int write_ef1)
{
    extern __shared__ uint32_t smem[];
    uint32_t* As = smem;                // [128][68] attention rows, tf32
    uint32_t* Bs = smem + FA_WORDS;     // [64][68]  Wo transposed [n][k], tf32

    const int tid = threadIdx.x;
    const int m0  = blockIdx.x * 128;
    const float* ef_in = use_ef1_in ? (const float*)g_ef1 : ef_ext;
    float* out = write_ef1 ? (float*)g_ef1 : out_ext;

    const int wid = tid >> 5, lane = tid & 31;

    // ---- load Wo -> Bs [n][k] (transposed, stride 68) ----
    {
        const int bk = tid & 31;
        const int bn = (tid >> 5) * 8;
        #pragma unroll
        for (int k0 = 0; k0 < 64; k0 += 32) {
            float4 bv0 = *reinterpret_cast<const float4*>(Wo + (size_t)(k0 + bk) * 64 + bn);
            float4 bv1 = *reinterpret_cast<const float4*>(Wo + (size_t)(k0 + bk) * 64 + bn + 4);
            float vv[8] = {bv0.x, bv0.y, bv0.z, bv0.w, bv1.x, bv1.y, bv1.z, bv1.w};
            #pragma unroll
            for (int j = 0; j < 8; j++)
                Bs[(bn + j) * FSTRIDE + k0 + bk] = f2tf(vv[j]);
        }
    }

    // ---- phase 1: attention into As (minimal live registers) ----
    {
        const int sub = lane >> 4, l16 = lane & 15;
        #pragma unroll
        for (int iter = 0; iter < 8; iter++) {
            const int el = iter * 16 + wid * 2 + sub;
            const int e = m0 + el;
            const int ec = (e < EE) ? e : (EE - 1);   // clamp: keeps shuffles convergent

            const float* qrow = g_qkv + (size_t)ec * DIN;
            float4 q = *reinterpret_cast<const float4*>(qrow + 4 * l16);
            const int base = ec * KNB;

            // pass 1: scores (nb + K rows in chunks of 4)
            float sj[KNB];
            #pragma unroll
            for (int c = 0; c < 2; c++) {
                int nb4[4];
                #pragma unroll
                for (int j = 0; j < 4; j++) nb4[j] = adj_src[base + c * 4 + j];
                float4 kk[4];
                #pragma unroll
                for (int j = 0; j < 4; j++)
                    kk[j] = *reinterpret_cast<const float4*>(
                        g_qkv + (size_t)nb4[j] * DIN + 64 + 4 * l16);
                #pragma unroll
                for (int j = 0; j < 4; j++) {
                    float p = q.x * kk[j].x + q.y * kk[j].y + q.z * kk[j].z + q.w * kk[j].w;
                    p += __shfl_xor_sync(0xffffffffu, p, 1);
                    p += __shfl_xor_sync(0xffffffffu, p, 2);   // head-local (4 lanes)
                    sj[c * 4 + j] = p * 0.25f;                  // 1/sqrt(16)
                }
            }

            float m = sj[0];
            #pragma unroll
            for (int j = 1; j < KNB; j++) m = fmaxf(m, sj[j]);

            // pass 2: weighted V accumulation (nb + V rows in chunks of 4)
            float denom = 0.f;
            float4 a = make_float4(0.f, 0.f, 0.f, 0.f);
            #pragma unroll
            for (int c = 0; c < 2; c++) {
                int nb4[4];
                #pragma unroll
                for (int j = 0; j < 4; j++) nb4[j] = adj_src[base + c * 4 + j];
                float4 vv[4];
                #pragma unroll
                for (int j = 0; j < 4; j++)
                    vv[j] = *reinterpret_cast<const float4*>(
                        g_qkv + (size_t)nb4[j] * DIN + 128 + 4 * l16);
                #pragma unroll
                for (int j = 0; j < 4; j++) {
                    float w = __expf(sj[c * 4 + j] - m);
                    denom += w;
                    a.x += w * vv[j].x; a.y += w * vv[j].y;
                    a.z += w * vv[j].z; a.w += w * vv[j].w;
                }
            }
            float inv = 1.0f / denom;
            uint4 o = make_uint4(f2tf(a.x * inv), f2tf(a.y * inv),
                                 f2tf(a.z * inv), f2tf(a.w * inv));
            *reinterpret_cast<uint4*>(&As[el * FSTRIDE + 4 * l16]) = o;
        }
    }
    __syncthreads();

    // ---- phase 2: GEMM 128x64x64 + residual ----
    const int wm = (wid & 3) * 32, wn = (wid >> 2) * 32;
    const int g = lane >> 2, t4 = lane & 3;
    const int j8 = lane & 7, grp = lane >> 3;

    const uint32_t As_b = (uint32_t)__cvta_generic_to_shared(As);
    const uint32_t Bs_b = (uint32_t)__cvta_generic_to_shared(Bs);
    uint32_t aAddr[2], bAddr[2];
    #pragma unroll
    for (int mt = 0; mt < 2; mt++) {
        int row = wm + mt * 16 + (grp & 1) * 8 + j8;
        int col = (grp >> 1) * 4;
        aAddr[mt] = As_b + (row * FSTRIDE + col) * 4;
    }
    #pragma unroll
    for (int p = 0; p < 2; p++) {
        int row = wn + p * 16 + (grp >> 1) * 8 + j8;
        int col = (grp & 1) * 4;
        bAddr[p] = Bs_b + (row * FSTRIDE + col) * 4;
    }

    float acc[2][4][4];
    #pragma unroll
    for (int i = 0; i < 2; i++)
        #pragma unroll
        for (int j = 0; j < 4; j++)
            #pragma unroll
            for (int q = 0; q < 4; q++) acc[i][j][q] = 0.f;

    #pragma unroll
    for (int ks = 0; ks < 8; ks++) {
        uint32_t af0[4], af1[4], bf0[4], bf1[4];
        ldsm4(af0, aAddr[0] + ks * 32);
        ldsm4(af1, aAddr[1] + ks * 32);
        ldsm4(bf0, bAddr[0] + ks * 32);
        ldsm4(bf1, bAddr[1] + ks * 32);
        mma8(acc[0][0], af0, bf0[0], bf0[1]);
        mma8(acc[0][1], af0, bf0[2], bf0[3]);
        mma8(acc[0][2], af0, bf1[0], bf1[1]);
        mma8(acc[0][3], af0, bf1[2], bf1[3]);
        mma8(acc[1][0], af1, bf0[0], bf0[1]);
        mma8(acc[1][1], af1, bf0[2], bf0[3]);
        mma8(acc[1][2], af1, bf1[0], bf1[1]);
        mma8(acc[1][3], af1, bf1[2], bf1[3]);
    }

    // ---- epilogue with residual ----
    #pragma unroll
    for (int mt = 0; mt < 2; mt++) {
        const int row = m0 + wm + mt * 16 + g;
        #pragma unroll
        for (int nt = 0; nt < 4; nt++) {
            const int col = wn + nt * 8 + t4 * 2;
            if (row < EE) {
                float2 rr = *reinterpret_cast<const float2*>(ef_in + (size_t)row * 64 + col);
                *reinterpret_cast<float2*>(out + (size_t)row * 64 + col) =
                    make_float2(rr.x + acc[mt][nt][0], rr.y + acc[mt][nt][1]);
            }
            if (row + 8 < EE) {
                float2 rr = *reinterpret_cast<const float2*>(ef_in + (size_t)(row + 8) * 64 + col);
                *reinterpret_cast<float2*>(out + (size_t)(row + 8) * 64 + col) =
                    make_float2(rr.x + acc[mt][nt][2], rr.y + acc[mt][nt][3]);
            }
        }
    }
}

// ---------------- launch ----------------
extern "C" void kernel_launch(void* const* d_in, const int* in_sizes, int n_in,
                              void* d_out, int out_size) {
    const float* nf      = (const float*)d_in[0];
    const float* ef      = (const float*)d_in[1];
    const int*   ei      = (const int*)d_in[2];
    const int*   adj_src = (const int*)d_in[4];
    const float* l1_Wq = (const float*)d_in[6];
    const float* l1_Wk = (const float*)d_in[7];
    const float* l1_Wv = (const float*)d_in[8];
    const float* l1_Wo = (const float*)d_in[9];
    const float* l2_Wq = (const float*)d_in[10];
    const float* l2_Wk = (const float*)d_in[11];
    const float* l2_Wv = (const float*)d_in[12];
    const float* l2_Wo = (const float*)d_in[13];
    float* out = (float*)d_out;

    static int attr_done = 0;
    if (!attr_done) {
        cudaFuncSetAttribute(qkv_mma_kernel, cudaFuncAttributeMaxDynamicSharedMemorySize, QKV_SMEM_BYTES);
        cudaFuncSetAttribute(attn_wo_kernel, cudaFuncAttributeMaxDynamicSharedMemorySize, FUSED_SMEM_BYTES);
        attr_done = 1;
    }

    const int gq = (EE + 127) / 128;   // 782
    const int gf = (EE + 127) / 128;   // 782

    // layer 1
    qkv_mma_kernel<<<gq, 256, QKV_SMEM_BYTES>>>(ef, nf, ei, l1_Wq, l1_Wk, l1_Wv, 0);
    attn_wo_kernel<<<gf, 256, FUSED_SMEM_BYTES>>>(l1_Wo, adj_src, ef, nullptr, 0, 1);

    // layer 2
    qkv_mma_kernel<<<gq, 256, QKV_SMEM_BYTES>>>(ef, nf, ei, l2_Wq, l2_Wk, l2_Wv, 1);
    attn_wo_kernel<<<gf, 256, FUSED_SMEM_BYTES>>>(l2_Wo, adj_src, nullptr, out, 1, 0);
}

// round 13
// speedup vs baseline: 1.2102x; 1.2102x over previous
#include <cuda_runtime.h>
#include <stdint.h>

#define EE     100000
#define DIN    192
#define KNB    8

// ---------------- scratch (device globals) ----------------
__device__ float g_qkv[EE * DIN];   // [E,192] = [q|k|v]
__device__ float g_ef1[EE * 64];    // [E,64] layer-1 out

// ---------------- helpers ----------------
__device__ __forceinline__ uint32_t f2tf(float x) {
    uint32_t u; asm("cvt.rna.tf32.f32 %0, %1;" : "=r"(u) : "f"(x)); return u;
}
__device__ __forceinline__ void mma8(float* c, const uint32_t* a, uint32_t b0, uint32_t b1) {
    asm volatile("mma.sync.aligned.m16n8k8.row.col.f32.tf32.tf32.f32 "
        "{%0,%1,%2,%3}, {%4,%5,%6,%7}, {%8,%9}, {%0,%1,%2,%3};"
        : "+f"(c[0]), "+f"(c[1]), "+f"(c[2]), "+f"(c[3])
        : "r"(a[0]), "r"(a[1]), "r"(a[2]), "r"(a[3]), "r"(b0), "r"(b1));
}
__device__ __forceinline__ void ldsm4(uint32_t* f, uint32_t addr) {
    asm volatile("ldmatrix.sync.aligned.m8n8.x4.shared.b16 {%0,%1,%2,%3}, [%4];"
        : "=r"(f[0]), "=r"(f[1]), "=r"(f[2]), "=r"(f[3]) : "r"(addr));
}

// ---------------- QKV kernel smem geometry (r4/r9 proven) ----------------
#define BSTRIDE    200
#define B_WORDS_F  (192 * BSTRIDE)      // 38400
#define A_WORDS    (128 * 36)           // 4608
#define QKV_SMEM_BYTES ((B_WORDS_F + 2 * A_WORDS) * 4)

// ---------------- fused attn+wo smem geometry ----------------
#define FSTRIDE    68                    // 68 % 32 == 4 -> conflict-free ldsm/STS
#define FA_WORDS   (128 * FSTRIDE)       // 8704
#define FB_WORDS   (64 * FSTRIDE)        // 4352
#define FUSED_SMEM_BYTES ((FA_WORDS + FB_WORDS) * 4)   // 52224

// ======================================================================
// Fused QKV GEMM (r4/r9 proven): qkv = concat(ef|ef1, nf[src], nf[dst]) @ [Wq|Wk|Wv]
// BM=128, BN=192, BK=32; 8 warps as 2M x 4N, warp tile 64x48.
// ======================================================================
__global__ __launch_bounds__(256, 1) void qkv_mma_kernel(
    const float* __restrict__ ef, const float* __restrict__ nf,
    const int* __restrict__ ei,
    const float* __restrict__ wq, const float* __restrict__ wk, const float* __restrict__ wv,
    int use_ef1)
{
    extern __shared__ uint32_t smem[];
    uint32_t* Bs = smem;                 // [192][200]
    uint32_t* As = smem + B_WORDS_F;     // [2][128*36]

    const int tid = threadIdx.x;
    const int m0  = blockIdx.x * 128;
    const float* efsrc = use_ef1 ? (const float*)g_ef1 : ef;

    const int r  = tid >> 1;
    const int e  = m0 + r;
    const int kb = (tid & 1) * 16;
    const bool valid = (e < EE);
    int si = 0, di = 0;
    if (valid) { si = ei[e]; di = ei[EE + e]; }

    const int wid = tid >> 5, lane = tid & 31;
    const int wm = (wid & 1) * 64, wn = (wid >> 1) * 48;
    const int g = lane >> 2, t4 = lane & 3;
    const int j8 = lane & 7, grp = lane >> 3;

    // ---- preload full B into smem (tf32) ----
    {
        #pragma unroll
        for (int w = 0; w < 3; w++) {
            const float* W = (w == 0) ? wq : (w == 1) ? wk : wv;
            #pragma unroll
            for (int j = 0; j < 12; j++) {
                int f = j * 256 + tid;
                int k = f >> 4;
                int n4 = (f & 15) * 4;
                float4 v = *reinterpret_cast<const float4*>(W + (size_t)k * 64 + n4);
                uint32_t* dst = Bs + k * BSTRIDE + w * 64 + n4;
                dst[0] = f2tf(v.x); dst[1] = f2tf(v.y);
                dst[2] = f2tf(v.z); dst[3] = f2tf(v.w);
            }
        }
    }

    const uint32_t As_b = (uint32_t)__cvta_generic_to_shared(As);
    uint32_t aAddr[4];
    #pragma unroll
    for (int mt = 0; mt < 4; mt++) {
        int row = wm + mt * 16 + (grp & 1) * 8 + j8;
        int col = (grp >> 1) * 4;
        aAddr[mt] = As_b + (row * 36 + col) * 4;
    }

    float acc[4][6][4];
    #pragma unroll
    for (int i = 0; i < 4; i++)
        #pragma unroll
        for (int j = 0; j < 6; j++)
            #pragma unroll
            for (int q = 0; q < 4; q++) acc[i][j][q] = 0.f;

    float4 av[4];
    auto ldg_tile = [&](int it) {
        const int k0 = it * 32;
        if (valid) {
            const int reg = k0 >> 6;
            const float* base = (reg == 0) ? efsrc + (size_t)e * 64
                              : (reg == 1) ? nf + (size_t)si * 64
                                           : nf + (size_t)di * 64;
            const int cb = (k0 & 32) + kb;
            #pragma unroll
            for (int c = 0; c < 4; c++) av[c] = *reinterpret_cast<const float4*>(base + cb + c * 4);
        } else {
            #pragma unroll
            for (int c = 0; c < 4; c++) av[c] = make_float4(0.f, 0.f, 0.f, 0.f);
        }
    };
    auto sts_tile = [&](int b) {
        uint32_t* Aw = As + b * A_WORDS;
        #pragma unroll
        for (int c = 0; c < 4; c++) {
            uint4 u = make_uint4(f2tf(av[c].x), f2tf(av[c].y), f2tf(av[c].z), f2tf(av[c].w));
            *reinterpret_cast<uint4*>(&Aw[r * 36 + kb + c * 4]) = u;
        }
    };

    const uint32_t* Bwp = Bs + wn + g;

    const int NIT = DIN / 32;   // 6
    ldg_tile(0);
    sts_tile(0);
    ldg_tile(1);
    __syncthreads();

    for (int i = 0; i < NIT; i++) {
        const int cur = i & 1;
        const uint32_t aOff = cur * (A_WORDS * 4);
        #pragma unroll
        for (int ks = 0; ks < 4; ks++) {
            const int kg = i * 32 + ks * 8 + t4;
            uint32_t af[4][4];
            #pragma unroll
            for (int mt = 0; mt < 4; mt++) ldsm4(af[mt], aAddr[mt] + aOff + ks * 32);
            uint32_t b0[6], b1[6];
            #pragma unroll
            for (int nt = 0; nt < 6; nt++) {
                b0[nt] = Bwp[kg * BSTRIDE + nt * 8];
                b1[nt] = Bwp[(kg + 4) * BSTRIDE + nt * 8];
            }
            #pragma unroll
            for (int mt = 0; mt < 4; mt++)
                #pragma unroll
                for (int nt = 0; nt < 6; nt++)
                    mma8(acc[mt][nt], af[mt], b0[nt], b1[nt]);
        }
        if (i + 1 < NIT) {
            sts_tile(cur ^ 1);
            if (i + 2 < NIT) ldg_tile(i + 2);
            __syncthreads();
        }
    }

    #pragma unroll
    for (int mt = 0; mt < 4; mt++) {
        const int row = m0 + wm + mt * 16 + g;
        #pragma unroll
        for (int nt = 0; nt < 6; nt++) {
            const int col = wn + nt * 8 + t4 * 2;
            if (row < EE)
                *reinterpret_cast<float2*>(g_qkv + (size_t)row * DIN + col) =
                    make_float2(acc[mt][nt][0], acc[mt][nt][1]);
            if (row + 8 < EE)
                *reinterpret_cast<float2*>(g_qkv + (size_t)(row + 8) * DIN + col) =
                    make_float2(acc[mt][nt][2], acc[mt][nt][3]);
        }
    }
}

// ======================================================================
// FUSED attention + Wo GEMM + residual — low-register two-pass attn (r11).
// Phase 1: 128 dst edges/CTA, attention -> As tf32 (K chunked, V chunked)
// Phase 2: out = ef_in + As[128,64] @ Wo[64,64]
// ======================================================================
__global__ __launch_bounds__(256, 3) void attn_wo_kernel(
    const float* __restrict__ Wo,
    const int* __restrict__ adj_src,
    const float* __restrict__ ef_ext, float* __restrict__ out_ext,
    int use_ef1_in, int write_ef1)
{
    extern __shared__ uint32_t smem[];
    uint32_t* As = smem;                // [128][68] attention rows, tf32
    uint32_t* Bs = smem + FA_WORDS;     // [64][68]  Wo transposed [n][k], tf32

    const int tid = threadIdx.x;
    const int m0  = blockIdx.x * 128;
    const float* ef_in = use_ef1_in ? (const float*)g_ef1 : ef_ext;
    float* out = write_ef1 ? (float*)g_ef1 : out_ext;

    const int wid = tid >> 5, lane = tid & 31;

    // ---- load Wo -> Bs [n][k] (transposed, stride 68) ----
    {
        const int bk = tid & 31;
        const int bn = (tid >> 5) * 8;
        #pragma unroll
        for (int k0 = 0; k0 < 64; k0 += 32) {
            float4 bv0 = *reinterpret_cast<const float4*>(Wo + (size_t)(k0 + bk) * 64 + bn);
            float4 bv1 = *reinterpret_cast<const float4*>(Wo + (size_t)(k0 + bk) * 64 + bn + 4);
            float vv[8] = {bv0.x, bv0.y, bv0.z, bv0.w, bv1.x, bv1.y, bv1.z, bv1.w};
            #pragma unroll
            for (int j = 0; j < 8; j++)
                Bs[(bn + j) * FSTRIDE + k0 + bk] = f2tf(vv[j]);
        }
    }

    // ---- phase 1: attention into As (chunked, low-register) ----
    {
        const int sub = lane >> 4, l16 = lane & 15;
        #pragma unroll
        for (int iter = 0; iter < 8; iter++) {
            const int el = iter * 16 + wid * 2 + sub;
            const int e = m0 + el;
            const int ec = (e < EE) ? e : (EE - 1);   // clamp: keeps shuffles convergent

            const float* qrow = g_qkv + (size_t)ec * DIN;
            float4 q = *reinterpret_cast<const float4*>(qrow + 4 * l16);

            int nb[KNB];
            const int base = ec * KNB;
            #pragma unroll
            for (int j = 0; j < KNB; j++) nb[j] = adj_src[base + j];

            // pass 1: scores (K rows in chunks of 4)
            float sj[KNB];
            #pragma unroll
            for (int c = 0; c < 2; c++) {
                float4 kk[4];
                #pragma unroll
                for (int j = 0; j < 4; j++)
                    kk[j] = *reinterpret_cast<const float4*>(
                        g_qkv + (size_t)nb[c * 4 + j] * DIN + 64 + 4 * l16);
                #pragma unroll
                for (int j = 0; j < 4; j++) {
                    float p = q.x * kk[j].x + q.y * kk[j].y + q.z * kk[j].z + q.w * kk[j].w;
                    p += __shfl_xor_sync(0xffffffffu, p, 1);
                    p += __shfl_xor_sync(0xffffffffu, p, 2);   // head-local (4 lanes)
                    sj[c * 4 + j] = p * 0.25f;                  // 1/sqrt(16)
                }
            }

            float m = sj[0];
            #pragma unroll
            for (int j = 1; j < KNB; j++) m = fmaxf(m, sj[j]);

            // pass 2: weighted V accumulation (V rows in chunks of 4)
            float denom = 0.f;
            float4 a = make_float4(0.f, 0.f, 0.f, 0.f);
            #pragma unroll
            for (int c = 0; c < 2; c++) {
                float4 vv[4];
                #pragma unroll
                for (int j = 0; j < 4; j++)
                    vv[j] = *reinterpret_cast<const float4*>(
                        g_qkv + (size_t)nb[c * 4 + j] * DIN + 128 + 4 * l16);
                #pragma unroll
                for (int j = 0; j < 4; j++) {
                    float w = __expf(sj[c * 4 + j] - m);
                    denom += w;
                    a.x += w * vv[j].x; a.y += w * vv[j].y;
                    a.z += w * vv[j].z; a.w += w * vv[j].w;
                }
            }
            float inv = 1.0f / denom;
            uint4 o = make_uint4(f2tf(a.x * inv), f2tf(a.y * inv),
                                 f2tf(a.z * inv), f2tf(a.w * inv));
            *reinterpret_cast<uint4*>(&As[el * FSTRIDE + 4 * l16]) = o;
        }
    }
    __syncthreads();

    // ---- phase 2: GEMM 128x64x64 + residual ----
    const int wm = (wid & 3) * 32, wn = (wid >> 2) * 32;
    const int g = lane >> 2, t4 = lane & 3;
    const int j8 = lane & 7, grp = lane >> 3;

    const uint32_t As_b = (uint32_t)__cvta_generic_to_shared(As);
    const uint32_t Bs_b = (uint32_t)__cvta_generic_to_shared(Bs);
    uint32_t aAddr[2], bAddr[2];
    #pragma unroll
    for (int mt = 0; mt < 2; mt++) {
        int row = wm + mt * 16 + (grp & 1) * 8 + j8;
        int col = (grp >> 1) * 4;
        aAddr[mt] = As_b + (row * FSTRIDE + col) * 4;
    }
    #pragma unroll
    for (int p = 0; p < 2; p++) {
        int row = wn + p * 16 + (grp >> 1) * 8 + j8;
        int col = (grp & 1) * 4;
        bAddr[p] = Bs_b + (row * FSTRIDE + col) * 4;
    }

    float acc[2][4][4];
    #pragma unroll
    for (int i = 0; i < 2; i++)
        #pragma unroll
        for (int j = 0; j < 4; j++)
            #pragma unroll
            for (int q = 0; q < 4; q++) acc[i][j][q] = 0.f;

    #pragma unroll
    for (int ks = 0; ks < 8; ks++) {
        uint32_t af0[4], af1[4], bf0[4], bf1[4];
        ldsm4(af0, aAddr[0] + ks * 32);
        ldsm4(af1, aAddr[1] + ks * 32);
        ldsm4(bf0, bAddr[0] + ks * 32);
        ldsm4(bf1, bAddr[1] + ks * 32);
        mma8(acc[0][0], af0, bf0[0], bf0[1]);
        mma8(acc[0][1], af0, bf0[2], bf0[3]);
        mma8(acc[0][2], af0, bf1[0], bf1[1]);
        mma8(acc[0][3], af0, bf1[2], bf1[3]);
        mma8(acc[1][0], af1, bf0[0], bf0[1]);
        mma8(acc[1][1], af1, bf0[2], bf0[3]);
        mma8(acc[1][2], af1, bf1[0], bf1[1]);
        mma8(acc[1][3], af1, bf1[2], bf1[3]);
    }

    // ---- epilogue with residual ----
    #pragma unroll
    for (int mt = 0; mt < 2; mt++) {
        const int row = m0 + wm + mt * 16 + g;
        #pragma unroll
        for (int nt = 0; nt < 4; nt++) {
            const int col = wn + nt * 8 + t4 * 2;
            if (row < EE) {
                float2 rr = *reinterpret_cast<const float2*>(ef_in + (size_t)row * 64 + col);
                *reinterpret_cast<float2*>(out + (size_t)row * 64 + col) =
                    make_float2(rr.x + acc[mt][nt][0], rr.y + acc[mt][nt][1]);
            }
            if (row + 8 < EE) {
                float2 rr = *reinterpret_cast<const float2*>(ef_in + (size_t)(row + 8) * 64 + col);
                *reinterpret_cast<float2*>(out + (size_t)(row + 8) * 64 + col) =
                    make_float2(rr.x + acc[mt][nt][2], rr.y + acc[mt][nt][3]);
            }
        }
    }
}

// ---------------- launch ----------------
extern "C" void kernel_launch(void* const* d_in, const int* in_sizes, int n_in,
                              void* d_out, int out_size) {
    const float* nf      = (const float*)d_in[0];
    const float* ef      = (const float*)d_in[1];
    const int*   ei      = (const int*)d_in[2];
    const int*   adj_src = (const int*)d_in[4];
    const float* l1_Wq = (const float*)d_in[6];
    const float* l1_Wk = (const float*)d_in[7];
    const float* l1_Wv = (const float*)d_in[8];
    const float* l1_Wo = (const float*)d_in[9];
    const float* l2_Wq = (const float*)d_in[10];
    const float* l2_Wk = (const float*)d_in[11];
    const float* l2_Wv = (const float*)d_in[12];
    const float* l2_Wo = (const float*)d_in[13];
    float* out = (float*)d_out;

    static int attr_done = 0;
    if (!attr_done) {
        cudaFuncSetAttribute(qkv_mma_kernel, cudaFuncAttributeMaxDynamicSharedMemorySize, QKV_SMEM_BYTES);
        cudaFuncSetAttribute(attn_wo_kernel, cudaFuncAttributeMaxDynamicSharedMemorySize, FUSED_SMEM_BYTES);
        attr_done = 1;
    }

    const int gq = (EE + 127) / 128;   // 782
    const int gf = (EE + 127) / 128;   // 782

    // layer 1
    qkv_mma_kernel<<<gq, 256, QKV_SMEM_BYTES>>>(ef, nf, ei, l1_Wq, l1_Wk, l1_Wv, 0);
    attn_wo_kernel<<<gf, 256, FUSED_SMEM_BYTES>>>(l1_Wo, adj_src, ef, nullptr, 0, 1);

    // layer 2
    qkv_mma_kernel<<<gq, 256, QKV_SMEM_BYTES>>>(ef, nf, ei, l2_Wq, l2_Wk, l2_Wv, 1);
    attn_wo_kernel<<<gf, 256, FUSED_SMEM_BYTES>>>(l2_Wo, adj_src, nullptr, out, 1, 0);
}